// round 17
// baseline (speedup 1.0000x reference)
#include <cuda_runtime.h>
#include <cstdint>

#define D_MODEL  4096
#define REMAINED 4403
#define BATCH    32

#define SPLITK   8
#define KSPLIT   (D_MODEL / SPLITK)     // 512
#define KC       32                     // k per chunk
#define NCHUNK   (KSPLIT / KC)          // 16
#define STAGES   4
#define MTILE    128
#define NBLKM    ((REMAINED + MTILE - 1) / MTILE)   // 35
#define THREADS  256

#define OUT_ELEMS (BATCH * REMAINED)    // 140896

// raw fp32 smem rows: 32 fp32 + 8 pad = 40 fp32 = 160B.
// 160/4 = 40 == 8 (mod 32) -> 8 rows x 4 k-pairs per LDS.64 phase hit distinct banks.
#define RSTRB    160
#define W_SZ     (MTILE * RSTRB)        // 20480
#define X_OFF    W_SZ
#define STAGE_SZ (W_SZ + BATCH * RSTRB) // 25600
#define SM_TOTAL (STAGES * STAGE_SZ)    // 102400

__device__ float g_scratch[(size_t)SPLITK * OUT_ELEMS];   // ~4.5 MB
__device__ int   g_cnt[NBLKM];                            // zero-init, self-resetting

// ---------------- helpers ----------------
__device__ __forceinline__ uint32_t smem_u32(const void* p) {
    uint32_t a;
    asm("{ .reg .u64 t; cvta.to.shared.u64 t, %1; cvt.u32.u64 %0, t; }" : "=r"(a) : "l"(p));
    return a;
}
__device__ __forceinline__ uint32_t pack_hi(float a, float b) {
    uint32_t r;
    asm("prmt.b32 %0, %1, %2, 0x7632;" : "=r"(r)
        : "r"(__float_as_uint(a)), "r"(__float_as_uint(b)));
    return r;
}
__device__ __forceinline__ float hi_f(float v) {
    return __uint_as_float(__float_as_uint(v) & 0xFFFF0000u);
}
__device__ __forceinline__ uint32_t pack_lo(float e0, float e1) {
    uint32_t r;
    asm("cvt.rn.bf16x2.f32 %0, %1, %2;" : "=r"(r) : "f"(e1), "f"(e0));
    return r;
}
__device__ __forceinline__ float2 lds64(uint32_t a) {
    float2 v;
    asm volatile("ld.shared.v2.f32 {%0,%1}, [%2];" : "=f"(v.x), "=f"(v.y) : "r"(a));
    return v;
}
// one raw fp32 pair -> hi bf16x2 (truncate) + lo bf16x2 (exact residual, rn)
__device__ __forceinline__ void cvt_pair(float2 v, uint32_t& hi, uint32_t& lo) {
    hi = pack_hi(v.x, v.y);
    lo = pack_lo(v.x - hi_f(v.x), v.y - hi_f(v.y));
}
__device__ __forceinline__ void cp16(uint32_t dst, const void* src) {
    asm volatile("cp.async.cg.shared.global [%0], [%1], 16;" :: "r"(dst), "l"(src) : "memory");
}
#define CP_COMMIT() asm volatile("cp.async.commit_group;" ::: "memory")
#define CP_WAIT2()  asm volatile("cp.async.wait_group 2;" ::: "memory")

__device__ __forceinline__ void mma_bf16(float* c, const uint32_t* a, const uint32_t* b) {
    asm volatile("mma.sync.aligned.m16n8k16.row.col.f32.bf16.bf16.f32 "
        "{%0,%1,%2,%3}, {%4,%5,%6,%7}, {%8,%9}, {%0,%1,%2,%3};"
        : "+f"(c[0]), "+f"(c[1]), "+f"(c[2]), "+f"(c[3])
        : "r"(a[0]), "r"(a[1]), "r"(a[2]), "r"(a[3]), "r"(b[0]), "r"(b[1]));
}

// ---------------- fused GEMM + split-K reduce ----------------
__global__ void __launch_bounds__(THREADS, 2)
gemm_bf16x3(const float* __restrict__ x,      // [32, 4096]
            const float* __restrict__ w,      // [11008, 4096]
            const int*   __restrict__ idx,    // [4403]
            float*       __restrict__ out)    // [32, 4403]
{
    extern __shared__ __align__(16) char smem[];
    __shared__ int s_last;

    const int tid   = threadIdx.x;
    const int lane  = tid & 31;
    const int wq    = tid >> 5;
    const int mg    = wq >> 1;            // m-group 0..3 (32 rows)
    const int ng    = wq & 1;             // n-group 0..1 (16 batch)
    const int mbase = blockIdx.x * MTILE;
    const int k0    = blockIdx.y * KSPLIT;
    const uint32_t sb = smem_u32(smem);

    // ---- cp.async fill geometry (fixed rows per thread) ----
    // w: 2 threads per row, each 64B half (4 x cp16 per chunk)
    const int wrow_cp = tid >> 1;                      // 0..127
    int gn = mbase + wrow_cp; if (gn >= REMAINED) gn = REMAINED - 1;
    const char* wsrc = (const char*)(w + (size_t)idx[gn] * D_MODEL + k0) + (tid & 1) * 64;
    const uint32_t wdst = sb + (uint32_t)(wrow_cp * RSTRB + (tid & 1) * 64);
    // x: 8 threads per row, one 16B unit each
    const int xrow_cp = tid >> 3;                      // 0..31
    const char* xsrc = (const char*)(x + (size_t)xrow_cp * D_MODEL + k0) + (tid & 7) * 16;
    const uint32_t xdst = sb + (uint32_t)(X_OFF + xrow_cp * RSTRB + (tid & 7) * 16);

    // ---- consume geometry (PTX m16n8k16 fragment layout) ----
    const int g = lane >> 2;              // group 0..7
    const int t = lane & 3;               // thread-in-group
    // A: row = mg*32 + s*16 + g (+8), k = 2t (+8)   [raw fp32, so *4 bytes]
    const uint32_t aBase = (uint32_t)((mg * 32 + g) * RSTRB + t * 8);
    // B: n = ng*16 + nblk*8 + g, k = 2t (+8)
    const uint32_t bBase = (uint32_t)(X_OFF + (ng * 16 + g) * RSTRB + t * 8);

    float acc[2][2][4];
#pragma unroll
    for (int s = 0; s < 2; s++)
#pragma unroll
        for (int n = 0; n < 2; n++)
#pragma unroll
            for (int r = 0; r < 4; r++) acc[s][n][r] = 0.f;

    // ---- prologue: fill stages 0..2 ----
#pragma unroll
    for (int c = 0; c < STAGES - 1; c++) {
        const uint32_t stb = (uint32_t)(c * STAGE_SZ);
        const char* ws = wsrc + c * (KC * 4);
#pragma unroll
        for (int i = 0; i < 4; i++) cp16(wdst + stb + i * 16, ws + i * 16);
        cp16(xdst + stb, xsrc + c * (KC * 4));
        CP_COMMIT();
    }

#pragma unroll 1
    for (int c = 0; c < NCHUNK; c++) {
        CP_WAIT2();
        __syncthreads();                   // stage c&3 visible to all warps

        const uint32_t st = sb + (uint32_t)((c & 3) * STAGE_SZ);

        // compute chunk c: 2 k16 steps
#pragma unroll
        for (int ks = 0; ks < 2; ks++) {
            const uint32_t ka = (uint32_t)(ks * 64);   // 16 fp32
            uint32_t ahi[2][4], alo[2][4], bhi[4], blo[4];
#pragma unroll
            for (int s = 0; s < 2; s++) {
                const uint32_t ab = st + aBase + (uint32_t)(s * 16 * RSTRB) + ka;
                cvt_pair(lds64(ab),                    ahi[s][0], alo[s][0]);
                cvt_pair(lds64(ab + 8 * RSTRB),        ahi[s][1], alo[s][1]);
                cvt_pair(lds64(ab + 32),               ahi[s][2], alo[s][2]);
                cvt_pair(lds64(ab + 8 * RSTRB + 32),   ahi[s][3], alo[s][3]);
            }
#pragma unroll
            for (int n = 0; n < 2; n++) {
                const uint32_t bb = st + bBase + (uint32_t)(n * 8 * RSTRB) + ka;
                cvt_pair(lds64(bb),      bhi[2 * n + 0], blo[2 * n + 0]);
                cvt_pair(lds64(bb + 32), bhi[2 * n + 1], blo[2 * n + 1]);
            }
#pragma unroll
            for (int s = 0; s < 2; s++)
#pragma unroll
                for (int n = 0; n < 2; n++) {
                    mma_bf16(acc[s][n], ahi[s], bhi + 2 * n);
                    mma_bf16(acc[s][n], ahi[s], blo + 2 * n);
                    mma_bf16(acc[s][n], alo[s], bhi + 2 * n);
                }
        }

        // issue fill for chunk c+3 into stage (c+3)&3 (freed: last read at compute c-1)
        if (c + STAGES - 1 < NCHUNK) {
            const int cf = c + STAGES - 1;
            const uint32_t stb = (uint32_t)((cf & 3) * STAGE_SZ);
            const char* ws = wsrc + cf * (KC * 4);
#pragma unroll
            for (int i = 0; i < 4; i++) cp16(wdst + stb + i * 16, ws + i * 16);
            cp16(xdst + stb, xsrc + cf * (KC * 4));
        }
        CP_COMMIT();                       // unconditional: keeps group count uniform
    }

    // ---- epilogue: scatter to split scratch (same C-fragment map as before) ----
    float* scr = g_scratch + (size_t)blockIdx.y * OUT_ELEMS;
#pragma unroll
    for (int s = 0; s < 2; s++) {
        const int n_row0 = mbase + mg * 32 + s * 16 + g;
#pragma unroll
        for (int n = 0; n < 2; n++) {
            const int b0 = ng * 16 + n * 8 + 2 * t;
            if (n_row0 < REMAINED) {
                scr[(size_t)(b0 + 0) * REMAINED + n_row0] = acc[s][n][0];
                scr[(size_t)(b0 + 1) * REMAINED + n_row0] = acc[s][n][1];
            }
            if (n_row0 + 8 < REMAINED) {
                scr[(size_t)(b0 + 0) * REMAINED + n_row0 + 8] = acc[s][n][2];
                scr[(size_t)(b0 + 1) * REMAINED + n_row0 + 8] = acc[s][n][3];
            }
        }
    }

    // ---- fused deterministic reduce: last CTA of this m-tile sums 8 splits ----
    __threadfence();
    __syncthreads();
    if (tid == 0) s_last = atomicAdd(&g_cnt[blockIdx.x], 1);
    __syncthreads();
    if (s_last == SPLITK - 1) {
        __threadfence();
#pragma unroll 1
        for (int it = 0; it < (MTILE * BATCH) / THREADS; it++) {
            const int e = it * THREADS + tid;
            const int b = e >> 7;
            const int n = mbase + (e & 127);
            if (n < REMAINED) {
                const size_t o = (size_t)b * REMAINED + n;
                float s = 0.f;
#pragma unroll
                for (int sp = 0; sp < SPLITK; sp++)
                    s += g_scratch[(size_t)sp * OUT_ELEMS + o];
                out[o] = s;
            }
        }
        if (tid == 0) g_cnt[blockIdx.x] = 0;
    }
}

extern "C" void kernel_launch(void* const* d_in, const int* in_sizes, int n_in,
                              void* d_out, int out_size) {
    const float* x   = (const float*)d_in[0];
    const float* w   = (const float*)d_in[1];
    const int*   idx = (const int*)d_in[2];
    float*       out = (float*)d_out;

    static bool configured = false;
    if (!configured) {
        cudaFuncSetAttribute(gemm_bf16x3,
                             cudaFuncAttributeMaxDynamicSharedMemorySize, SM_TOTAL);
        configured = true;
    }

    dim3 grid(NBLKM, SPLITK);                 // 35 x 8 = 280 CTAs (2/SM)
    gemm_bf16x3<<<grid, THREADS, SM_TOTAL>>>(x, w, idx, out);
}